// round 10
// baseline (speedup 1.0000x reference)
#include <cuda_runtime.h>
#include <cuda_fp16.h>
#include <cstdint>

// LinearAttend: q,k,v [4][8][64][8192] f32 -> out same shape.
//   ks = softmax(k, axis=s); qs = softmax(q, axis=d) * D^-0.5
//   ctx = ks @ v^T (64x64/head); out = ctx^T @ qs
// fp16 m16n8k16 MMA (fp32 accum), ldmatrix feed, ex2.approx.f16x2 exps,
// Zk via ones-column MMA, atomic-free split-K partials.
// This round: ctx reverted to measured-best CHUNKS=8 config; out gets a
// smem-transposed epilogue for fully-coalesced float4 stores (fixes the
// 8-lines-per-STG fragment store pattern that saturated L1).

#define SQ 8192
#define DH 64
#define NHEADS 32
#define CHUNKS 8
#define CHUNK_S (SQ / CHUNKS)     // 1024 -> 16 tiles of 64
#define LOG2E 1.4426950408889634f

__device__ float  g_ctx_part[CHUNKS * NHEADS * DH * DH];  // 4 MB partials
__device__ float  g_zk_part[CHUNKS * NHEADS * DH];
__device__ __half g_ctxh[NHEADS * DH * DH];               // normalized ctx

__device__ __forceinline__ uint32_t smem_u32(const void* p) {
    return (uint32_t)__cvta_generic_to_shared(p);
}
__device__ __forceinline__ void cp_async16(uint32_t dst, const void* src) {
    asm volatile("cp.async.cg.shared.global [%0], [%1], 16;" :: "r"(dst), "l"(src));
}
__device__ __forceinline__ void cp_commit() {
    asm volatile("cp.async.commit_group;");
}
__device__ __forceinline__ void cp_wait1() {
    asm volatile("cp.async.wait_group 1;");
}
__device__ __forceinline__ void ldsm_x4(uint32_t* r, uint32_t a) {
    asm volatile("ldmatrix.sync.aligned.m8n8.x4.shared.b16 {%0,%1,%2,%3}, [%4];"
                 : "=r"(r[0]), "=r"(r[1]), "=r"(r[2]), "=r"(r[3]) : "r"(a));
}
__device__ __forceinline__ void ldsm_x2(uint32_t* r, uint32_t a) {
    asm volatile("ldmatrix.sync.aligned.m8n8.x2.shared.b16 {%0,%1}, [%2];"
                 : "=r"(r[0]), "=r"(r[1]) : "r"(a));
}
__device__ __forceinline__ void ldsm_x4t(uint32_t* r, uint32_t a) {
    asm volatile("ldmatrix.sync.aligned.m8n8.x4.trans.shared.b16 {%0,%1,%2,%3}, [%4];"
                 : "=r"(r[0]), "=r"(r[1]), "=r"(r[2]), "=r"(r[3]) : "r"(a));
}
__device__ __forceinline__ void mma_f16(float* d, const uint32_t* a, const uint32_t* b) {
    asm volatile(
        "mma.sync.aligned.m16n8k16.row.col.f32.f16.f16.f32 "
        "{%0,%1,%2,%3}, {%4,%5,%6,%7}, {%8,%9}, {%0,%1,%2,%3};"
        : "+f"(d[0]), "+f"(d[1]), "+f"(d[2]), "+f"(d[3])
        : "r"(a[0]), "r"(a[1]), "r"(a[2]), "r"(a[3]), "r"(b[0]), "r"(b[1]));
}
__device__ __forceinline__ uint32_t pack_h2(float hi, float lo) {
    uint32_t h;
    asm("cvt.rn.f16x2.f32 %0, %1, %2;" : "=r"(h) : "f"(hi), "f"(lo));
    return h;
}
__device__ __forceinline__ uint32_t ex2_h2(uint32_t y) {
    uint32_t r;
    asm("ex2.approx.f16x2 %0, %1;" : "=r"(r) : "r"(y));
    return r;
}

// ---------------------------------------------------------------------------
// Kernel 1: ctx partials. grid (CHUNKS, NHEADS), block 256.
// cp.async 2-stage staging, one barrier per tile. (r8 measured-best config)
// ---------------------------------------------------------------------------
#define CTX_SVF_OFF 32768
#define CTX_SA_OFF  65536
#define CTX_SB_OFF  83968
#define CTX_SMEM    104704

__global__ __launch_bounds__(256, 2) void ctx_kernel(const float* __restrict__ k,
                                                     const float* __restrict__ v) {
    extern __shared__ char dyn[];
    float* sKf = reinterpret_cast<float*>(dyn);
    float* sVf = reinterpret_cast<float*>(dyn + CTX_SVF_OFF);
    __half (*sAb)[72] = reinterpret_cast<__half(*)[72]>(dyn + CTX_SA_OFF);
    __half (*sBb)[72] = reinterpret_cast<__half(*)[72]>(dyn + CTX_SB_OFF);

    const int head = blockIdx.y;
    const int s0   = blockIdx.x * CHUNK_S;
    const int tid  = threadIdx.x;
    const int warp = tid >> 5;
    const int lane = tid & 31;
    const int wi   = warp & 3;
    const int wn   = warp >> 2;

    const float* kg = k + (size_t)head * DH * SQ;
    const float* vg = v + (size_t)head * DH * SQ;

    for (int e = tid; e < 2 * 8 * 36; e += 256) {
        const int stg = e / (8 * 36);
        const int rem = e % (8 * 36);
        const int row = 64 + rem / 36;
        *reinterpret_cast<uint32_t*>(&sBb[stg * 72 + row][(rem % 36) * 2]) =
            (row == 64) ? 0x3C003C00u : 0u;
    }

    const int r0 = tid >> 4;
    const int c4 = (tid & 15) * 4;

#pragma unroll
    for (int st = 0; st < 2; ++st) {
        const int scol = s0 + st * 64 + c4;
#pragma unroll
        for (int ib = 0; ib < 4; ++ib) {
            const int row = ib * 16 + r0;
            cp_async16(smem_u32(sKf + st * 4096 + row * 64 + c4), kg + (size_t)row * SQ + scol);
            cp_async16(smem_u32(sVf + st * 4096 + row * 64 + c4), vg + (size_t)row * SQ + scol);
        }
        cp_commit();
    }

    float acc[4][4];
#pragma unroll
    for (int n = 0; n < 4; ++n)
#pragma unroll
        for (int c = 0; c < 4; ++c) acc[n][c] = 0.0f;
    float accz[4] = {0.f, 0.f, 0.f, 0.f};

    const int NT = CHUNK_S / 64;    // 16
    for (int t = 0; t < NT; ++t) {
        const int st = t & 1;
        __half (*sA)[72] = sAb + st * 64;
        __half (*sB)[72] = sBb + st * 72;

        cp_wait1();

        const float* kf = sKf + st * 4096;
        const float* vf = sVf + st * 4096;
#pragma unroll
        for (int ib = 0; ib < 4; ++ib) {
            const int row = ib * 16 + r0;
            float4 kv = *reinterpret_cast<const float4*>(kf + row * 64 + c4);
            float4 vv = *reinterpret_cast<const float4*>(vf + row * 64 + c4);
            uint2 ek;
            ek.x = ex2_h2(pack_h2(kv.y * LOG2E, kv.x * LOG2E));
            ek.y = ex2_h2(pack_h2(kv.w * LOG2E, kv.z * LOG2E));
            *reinterpret_cast<uint2*>(&sA[row][c4]) = ek;
            uint2 vh;
            vh.x = pack_h2(vv.y, vv.x);
            vh.y = pack_h2(vv.w, vv.z);
            *reinterpret_cast<uint2*>(&sB[row][c4]) = vh;
        }

        if (t + 2 < NT) {
            const int scol = s0 + (t + 2) * 64 + c4;
#pragma unroll
            for (int ib = 0; ib < 4; ++ib) {
                const int row = ib * 16 + r0;
                cp_async16(smem_u32(sKf + st * 4096 + row * 64 + c4), kg + (size_t)row * SQ + scol);
                cp_async16(smem_u32(sVf + st * 4096 + row * 64 + c4), vg + (size_t)row * SQ + scol);
            }
        }
        cp_commit();

        __syncthreads();

#pragma unroll
        for (int kk = 0; kk < 4; ++kk) {
            uint32_t a[4];
            ldsm_x4(a, smem_u32(&sA[wi * 16 + (lane & 15)]
                                  [kk * 16 + (lane >> 4) * 8]));
#pragma unroll
            for (int np = 0; np < 2; ++np) {
                uint32_t b[4];
                ldsm_x4(b, smem_u32(&sB[wn * 32 + (np * 2 + (lane >> 4)) * 8 + (lane & 7)]
                                      [kk * 16 + ((lane >> 3) & 1) * 8]));
                mma_f16(acc[np * 2],     a, b);
                mma_f16(acc[np * 2 + 1], a, b + 2);
            }
            if (wn == 1) {
                uint32_t b2[2];
                ldsm_x2(b2, smem_u32(&sB[64 + (lane & 7)]
                                       [kk * 16 + ((lane >> 3) & 1) * 8]));
                mma_f16(accz, a, b2);
            }
        }
    }

    float* ctxp = g_ctx_part + ((size_t)blockIdx.x * NHEADS + head) * DH * DH;
    const int i0 = wi * 16 + (lane >> 2);
    const int jb = wn * 32 + (lane & 3) * 2;
#pragma unroll
    for (int n = 0; n < 4; ++n) {
        const int j = jb + n * 8;
        *reinterpret_cast<float2*>(&ctxp[i0 * 64 + j])       = make_float2(acc[n][0], acc[n][1]);
        *reinterpret_cast<float2*>(&ctxp[(i0 + 8) * 64 + j]) = make_float2(acc[n][2], acc[n][3]);
    }
    if (wn == 1 && (lane & 3) == 0) {
        float* zkp = g_zk_part + ((size_t)blockIdx.x * NHEADS + head) * DH;
        zkp[i0]     = accz[0];
        zkp[i0 + 8] = accz[2];
    }
}

// ---------------------------------------------------------------------------
// Kernel 1.5: sum partials, normalize: ctxh[i][j] = sum_c part[c]*0.125/Zk[i]
// grid NHEADS, block 256.
// ---------------------------------------------------------------------------
__global__ __launch_bounds__(256) void norm_kernel() {
    const int head = blockIdx.x;
    const int tid  = threadIdx.x;
    const int base = tid * 16;
    const int i    = base >> 6;

    float z = 0.0f;
#pragma unroll
    for (int c = 0; c < CHUNKS; ++c)
        z += g_zk_part[((size_t)c * NHEADS + head) * DH + i];
    const float inv = __fdividef(0.125f, z);

    float s[16];
#pragma unroll
    for (int x = 0; x < 16; ++x) s[x] = 0.0f;
#pragma unroll
    for (int c = 0; c < CHUNKS; ++c) {
        const float* p = g_ctx_part + ((size_t)c * NHEADS + head) * DH * DH + base;
#pragma unroll
        for (int x = 0; x < 4; ++x) {
            float4 f = *reinterpret_cast<const float4*>(p + x * 4);
            s[x * 4]     += f.x;
            s[x * 4 + 1] += f.y;
            s[x * 4 + 2] += f.z;
            s[x * 4 + 3] += f.w;
        }
    }
    uint4 o0, o1;
    o0.x = pack_h2(s[1] * inv,  s[0] * inv);
    o0.y = pack_h2(s[3] * inv,  s[2] * inv);
    o0.z = pack_h2(s[5] * inv,  s[4] * inv);
    o0.w = pack_h2(s[7] * inv,  s[6] * inv);
    o1.x = pack_h2(s[9] * inv,  s[8] * inv);
    o1.y = pack_h2(s[11] * inv, s[10] * inv);
    o1.z = pack_h2(s[13] * inv, s[12] * inv);
    o1.w = pack_h2(s[15] * inv, s[14] * inv);
    __half* och = g_ctxh + head * DH * DH + base;
    *reinterpret_cast<uint4*>(och)     = o0;
    *reinterpret_cast<uint4*>(och + 8) = o1;
}

// ---------------------------------------------------------------------------
// Kernel 2: out[j,s] = (1/Zq_s) * sum_i ctxh[i][j] * exp(q[i,s])
// grid (SQ/128, NHEADS), block 256, one 64j x 128s tile per CTA.
// Lean (r8) + smem-transposed epilogue: scaled accs staged through a reused
// smem buffer, then fully-coalesced per-warp float4 stores.
// ---------------------------------------------------------------------------
struct OutSmemPhase1 {
    __half sCt[64][72];    // [i][j] normalized half context
    __half sQ[64][136];    // [i][s] exp(q) half
    float  sZp[8][132];    // Zq partials
};
union OutSmem {
    OutSmemPhase1 p1;
    float sOut[64][132];   // epilogue staging [j][s]
};

__global__ __launch_bounds__(256, 4) void out_kernel(const float* __restrict__ q,
                                                     float* __restrict__ out) {
    __shared__ OutSmem sm;
    __shared__ float sCs[128];        // 1/Zq_s (persists across phases)

    const int head = blockIdx.y;
    const int s0   = blockIdx.x * 128;
    const int tid  = threadIdx.x;
    const int warp = tid >> 5;
    const int lane = tid & 31;

    const float* qg = q + (size_t)head * DH * SQ + s0;
    const int r  = tid >> 5;          // 0..7
    const int c4 = (tid & 31) * 4;    // 0..124

    // context tile: 256 threads x 2 uint4 = 8 KB (hits L2)
    {
        const uint4* src = reinterpret_cast<const uint4*>(g_ctxh + head * DH * DH);
        uint4 c0 = src[tid * 2];
        uint4 c1 = src[tid * 2 + 1];
        const int i = tid >> 2;
        const int j = (tid & 3) * 16;
        *reinterpret_cast<uint4*>(&sm.p1.sCt[i][j])     = c0;
        *reinterpret_cast<uint4*>(&sm.p1.sCt[i][j + 8]) = c1;
    }

    // q: two batches of 4 float4 (bounded register pressure)
    float4 zp = make_float4(0.f, 0.f, 0.f, 0.f);
#pragma unroll
    for (int half = 0; half < 2; ++half) {
        float4 qv[4];
#pragma unroll
        for (int ib = 0; ib < 4; ++ib) {
            const int d = (half * 4 + ib) * 8 + r;
            qv[ib] = *reinterpret_cast<const float4*>(qg + (size_t)d * SQ + c4);
        }
#pragma unroll
        for (int ib = 0; ib < 4; ++ib) {
            const int d = (half * 4 + ib) * 8 + r;
            uint2 eq;
            eq.x = ex2_h2(pack_h2(qv[ib].y * LOG2E, qv[ib].x * LOG2E));
            eq.y = ex2_h2(pack_h2(qv[ib].w * LOG2E, qv[ib].z * LOG2E));
            *reinterpret_cast<uint2*>(&sm.p1.sQ[d][c4]) = eq;
            float2 e0 = __half22float2(*reinterpret_cast<__half2*>(&eq.x));
            float2 e1 = __half22float2(*reinterpret_cast<__half2*>(&eq.y));
            zp.x += e0.x; zp.y += e0.y; zp.z += e1.x; zp.w += e1.y;
        }
    }
    *reinterpret_cast<float4*>(&sm.p1.sZp[r][c4]) = zp;
    __syncthreads();

    if (tid < 128) {
        float z = 0.0f;
#pragma unroll
        for (int d = 0; d < 8; ++d) z += sm.p1.sZp[d][tid];
        sCs[tid] = __fdividef(1.0f, z);
    }

    float acc[8][4];
#pragma unroll
    for (int n = 0; n < 8; ++n)
#pragma unroll
        for (int c = 0; c < 4; ++c) acc[n][c] = 0.0f;

    const int jw = (warp & 3) * 16;   // j offset
    const int sw = (warp >> 2) * 64;  // s offset

#pragma unroll
    for (int kk = 0; kk < 4; ++kk) {
        uint32_t a[4];
        ldsm_x4t(a, smem_u32(&sm.p1.sCt[kk * 16 + (lane & 7) + (lane >> 4) * 8]
                                        [jw + ((lane >> 3) & 1) * 8]));
#pragma unroll
        for (int np = 0; np < 4; ++np) {
            uint32_t b[4];
            ldsm_x4t(b, smem_u32(&sm.p1.sQ[kk * 16 + (lane & 7) + ((lane >> 3) & 1) * 8]
                                           [sw + (np * 2 + (lane >> 4)) * 8]));
            mma_f16(acc[np * 2],     a, b);
            mma_f16(acc[np * 2 + 1], a, b + 2);
        }
    }
    __syncthreads();   // sCs ready; sCt/sQ/sZp dead -> sOut may alias them

    // epilogue phase A: scale by 1/Zq_s, stage into smem [j][s]
    const int j0 = jw + (lane >> 2);
    const int sc = (lane & 3) * 2;
#pragma unroll
    for (int n = 0; n < 8; ++n) {
        const int s = sw + n * 8 + sc;
        const float inv0 = sCs[s];
        const float inv1 = sCs[s + 1];
        *reinterpret_cast<float2*>(&sm.sOut[j0][s]) =
            make_float2(acc[n][0] * inv0, acc[n][1] * inv1);
        *reinterpret_cast<float2*>(&sm.sOut[j0 + 8][s]) =
            make_float2(acc[n][2] * inv0, acc[n][3] * inv1);
    }
    __syncthreads();

    // epilogue phase B: coalesced float4 stores (512B contiguous per warp)
    float* og = out + (size_t)head * DH * SQ + s0;
#pragma unroll
    for (int ib = 0; ib < 8; ++ib) {
        const int d = ib * 8 + r;
        float4 wv = *reinterpret_cast<const float4*>(&sm.sOut[d][c4]);
        *reinterpret_cast<float4*>(og + (size_t)d * SQ + c4) = wv;
    }
}

// ---------------------------------------------------------------------------
extern "C" void kernel_launch(void* const* d_in, const int* in_sizes, int n_in,
                              void* d_out, int out_size) {
    const float* q = (const float*)d_in[0];
    const float* k = (const float*)d_in[1];
    const float* v = (const float*)d_in[2];
    float* out = (float*)d_out;

    cudaFuncSetAttribute(ctx_kernel, cudaFuncAttributeMaxDynamicSharedMemorySize, CTX_SMEM);

    ctx_kernel<<<dim3(CHUNKS, NHEADS), 256, CTX_SMEM>>>(k, v);
    norm_kernel<<<NHEADS, 256>>>();
    out_kernel<<<dim3(SQ / 128, NHEADS), 256>>>(q, out);
}

// round 11
// speedup vs baseline: 1.2571x; 1.2571x over previous
#include <cuda_runtime.h>
#include <cuda_fp16.h>
#include <cstdint>

// LinearAttend: q,k,v [4][8][64][8192] f32 -> out same shape.
//   ks = softmax(k, axis=s); qs = softmax(q, axis=d) * D^-0.5
//   ctx = ks @ v^T (64x64/head); out = ctx^T @ qs
// fp16 m16n8k16 MMA (fp32 accum), ldmatrix feed, ex2.approx.f16x2 exps,
// Zk via ones-column MMA, atomic-free split-K partials.
// This round: re-validate smem-transposed out epilogue on a clean run;
// q-load hoist above ctx-tile fetch; streaming (.cs) output stores.

#define SQ 8192
#define DH 64
#define NHEADS 32
#define CHUNKS 8
#define CHUNK_S (SQ / CHUNKS)     // 1024 -> 16 tiles of 64
#define LOG2E 1.4426950408889634f

__device__ float  g_ctx_part[CHUNKS * NHEADS * DH * DH];  // 4 MB partials
__device__ float  g_zk_part[CHUNKS * NHEADS * DH];
__device__ __half g_ctxh[NHEADS * DH * DH];               // normalized ctx

__device__ __forceinline__ uint32_t smem_u32(const void* p) {
    return (uint32_t)__cvta_generic_to_shared(p);
}
__device__ __forceinline__ void cp_async16(uint32_t dst, const void* src) {
    asm volatile("cp.async.cg.shared.global [%0], [%1], 16;" :: "r"(dst), "l"(src));
}
__device__ __forceinline__ void cp_commit() {
    asm volatile("cp.async.commit_group;");
}
__device__ __forceinline__ void cp_wait1() {
    asm volatile("cp.async.wait_group 1;");
}
__device__ __forceinline__ void ldsm_x4(uint32_t* r, uint32_t a) {
    asm volatile("ldmatrix.sync.aligned.m8n8.x4.shared.b16 {%0,%1,%2,%3}, [%4];"
                 : "=r"(r[0]), "=r"(r[1]), "=r"(r[2]), "=r"(r[3]) : "r"(a));
}
__device__ __forceinline__ void ldsm_x2(uint32_t* r, uint32_t a) {
    asm volatile("ldmatrix.sync.aligned.m8n8.x2.shared.b16 {%0,%1}, [%2];"
                 : "=r"(r[0]), "=r"(r[1]) : "r"(a));
}
__device__ __forceinline__ void ldsm_x4t(uint32_t* r, uint32_t a) {
    asm volatile("ldmatrix.sync.aligned.m8n8.x4.trans.shared.b16 {%0,%1,%2,%3}, [%4];"
                 : "=r"(r[0]), "=r"(r[1]), "=r"(r[2]), "=r"(r[3]) : "r"(a));
}
__device__ __forceinline__ void mma_f16(float* d, const uint32_t* a, const uint32_t* b) {
    asm volatile(
        "mma.sync.aligned.m16n8k16.row.col.f32.f16.f16.f32 "
        "{%0,%1,%2,%3}, {%4,%5,%6,%7}, {%8,%9}, {%0,%1,%2,%3};"
        : "+f"(d[0]), "+f"(d[1]), "+f"(d[2]), "+f"(d[3])
        : "r"(a[0]), "r"(a[1]), "r"(a[2]), "r"(a[3]), "r"(b[0]), "r"(b[1]));
}
__device__ __forceinline__ uint32_t pack_h2(float hi, float lo) {
    uint32_t h;
    asm("cvt.rn.f16x2.f32 %0, %1, %2;" : "=r"(h) : "f"(hi), "f"(lo));
    return h;
}
__device__ __forceinline__ uint32_t ex2_h2(uint32_t y) {
    uint32_t r;
    asm("ex2.approx.f16x2 %0, %1;" : "=r"(r) : "r"(y));
    return r;
}
__device__ __forceinline__ void stg_cs_v4(float* p, float4 v) {
    asm volatile("st.global.cs.v4.f32 [%0], {%1,%2,%3,%4};"
                 :: "l"(p), "f"(v.x), "f"(v.y), "f"(v.z), "f"(v.w) : "memory");
}

// ---------------------------------------------------------------------------
// Kernel 1: ctx partials. grid (CHUNKS, NHEADS), block 256.
// cp.async 2-stage staging, one barrier per tile. (r8 measured-best config)
// ---------------------------------------------------------------------------
#define CTX_SVF_OFF 32768
#define CTX_SA_OFF  65536
#define CTX_SB_OFF  83968
#define CTX_SMEM    104704

__global__ __launch_bounds__(256, 2) void ctx_kernel(const float* __restrict__ k,
                                                     const float* __restrict__ v) {
    extern __shared__ char dyn[];
    float* sKf = reinterpret_cast<float*>(dyn);
    float* sVf = reinterpret_cast<float*>(dyn + CTX_SVF_OFF);
    __half (*sAb)[72] = reinterpret_cast<__half(*)[72]>(dyn + CTX_SA_OFF);
    __half (*sBb)[72] = reinterpret_cast<__half(*)[72]>(dyn + CTX_SB_OFF);

    const int head = blockIdx.y;
    const int s0   = blockIdx.x * CHUNK_S;
    const int tid  = threadIdx.x;
    const int warp = tid >> 5;
    const int lane = tid & 31;
    const int wi   = warp & 3;
    const int wn   = warp >> 2;

    const float* kg = k + (size_t)head * DH * SQ;
    const float* vg = v + (size_t)head * DH * SQ;

    for (int e = tid; e < 2 * 8 * 36; e += 256) {
        const int stg = e / (8 * 36);
        const int rem = e % (8 * 36);
        const int row = 64 + rem / 36;
        *reinterpret_cast<uint32_t*>(&sBb[stg * 72 + row][(rem % 36) * 2]) =
            (row == 64) ? 0x3C003C00u : 0u;
    }

    const int r0 = tid >> 4;
    const int c4 = (tid & 15) * 4;

#pragma unroll
    for (int st = 0; st < 2; ++st) {
        const int scol = s0 + st * 64 + c4;
#pragma unroll
        for (int ib = 0; ib < 4; ++ib) {
            const int row = ib * 16 + r0;
            cp_async16(smem_u32(sKf + st * 4096 + row * 64 + c4), kg + (size_t)row * SQ + scol);
            cp_async16(smem_u32(sVf + st * 4096 + row * 64 + c4), vg + (size_t)row * SQ + scol);
        }
        cp_commit();
    }

    float acc[4][4];
#pragma unroll
    for (int n = 0; n < 4; ++n)
#pragma unroll
        for (int c = 0; c < 4; ++c) acc[n][c] = 0.0f;
    float accz[4] = {0.f, 0.f, 0.f, 0.f};

    const int NT = CHUNK_S / 64;    // 16
    for (int t = 0; t < NT; ++t) {
        const int st = t & 1;
        __half (*sA)[72] = sAb + st * 64;
        __half (*sB)[72] = sBb + st * 72;

        cp_wait1();

        const float* kf = sKf + st * 4096;
        const float* vf = sVf + st * 4096;
#pragma unroll
        for (int ib = 0; ib < 4; ++ib) {
            const int row = ib * 16 + r0;
            float4 kv = *reinterpret_cast<const float4*>(kf + row * 64 + c4);
            float4 vv = *reinterpret_cast<const float4*>(vf + row * 64 + c4);
            uint2 ek;
            ek.x = ex2_h2(pack_h2(kv.y * LOG2E, kv.x * LOG2E));
            ek.y = ex2_h2(pack_h2(kv.w * LOG2E, kv.z * LOG2E));
            *reinterpret_cast<uint2*>(&sA[row][c4]) = ek;
            uint2 vh;
            vh.x = pack_h2(vv.y, vv.x);
            vh.y = pack_h2(vv.w, vv.z);
            *reinterpret_cast<uint2*>(&sB[row][c4]) = vh;
        }

        if (t + 2 < NT) {
            const int scol = s0 + (t + 2) * 64 + c4;
#pragma unroll
            for (int ib = 0; ib < 4; ++ib) {
                const int row = ib * 16 + r0;
                cp_async16(smem_u32(sKf + st * 4096 + row * 64 + c4), kg + (size_t)row * SQ + scol);
                cp_async16(smem_u32(sVf + st * 4096 + row * 64 + c4), vg + (size_t)row * SQ + scol);
            }
        }
        cp_commit();

        __syncthreads();

#pragma unroll
        for (int kk = 0; kk < 4; ++kk) {
            uint32_t a[4];
            ldsm_x4(a, smem_u32(&sA[wi * 16 + (lane & 15)]
                                  [kk * 16 + (lane >> 4) * 8]));
#pragma unroll
            for (int np = 0; np < 2; ++np) {
                uint32_t b[4];
                ldsm_x4(b, smem_u32(&sB[wn * 32 + (np * 2 + (lane >> 4)) * 8 + (lane & 7)]
                                      [kk * 16 + ((lane >> 3) & 1) * 8]));
                mma_f16(acc[np * 2],     a, b);
                mma_f16(acc[np * 2 + 1], a, b + 2);
            }
            if (wn == 1) {
                uint32_t b2[2];
                ldsm_x2(b2, smem_u32(&sB[64 + (lane & 7)]
                                       [kk * 16 + ((lane >> 3) & 1) * 8]));
                mma_f16(accz, a, b2);
            }
        }
    }

    float* ctxp = g_ctx_part + ((size_t)blockIdx.x * NHEADS + head) * DH * DH;
    const int i0 = wi * 16 + (lane >> 2);
    const int jb = wn * 32 + (lane & 3) * 2;
#pragma unroll
    for (int n = 0; n < 4; ++n) {
        const int j = jb + n * 8;
        *reinterpret_cast<float2*>(&ctxp[i0 * 64 + j])       = make_float2(acc[n][0], acc[n][1]);
        *reinterpret_cast<float2*>(&ctxp[(i0 + 8) * 64 + j]) = make_float2(acc[n][2], acc[n][3]);
    }
    if (wn == 1 && (lane & 3) == 0) {
        float* zkp = g_zk_part + ((size_t)blockIdx.x * NHEADS + head) * DH;
        zkp[i0]     = accz[0];
        zkp[i0 + 8] = accz[2];
    }
}

// ---------------------------------------------------------------------------
// Kernel 1.5: sum partials, normalize: ctxh[i][j] = sum_c part[c]*0.125/Zk[i]
// grid NHEADS, block 256.
// ---------------------------------------------------------------------------
__global__ __launch_bounds__(256) void norm_kernel() {
    const int head = blockIdx.x;
    const int tid  = threadIdx.x;
    const int base = tid * 16;
    const int i    = base >> 6;

    float z = 0.0f;
#pragma unroll
    for (int c = 0; c < CHUNKS; ++c)
        z += g_zk_part[((size_t)c * NHEADS + head) * DH + i];
    const float inv = __fdividef(0.125f, z);

    float s[16];
#pragma unroll
    for (int x = 0; x < 16; ++x) s[x] = 0.0f;
#pragma unroll
    for (int c = 0; c < CHUNKS; ++c) {
        const float* p = g_ctx_part + ((size_t)c * NHEADS + head) * DH * DH + base;
#pragma unroll
        for (int x = 0; x < 4; ++x) {
            float4 f = *reinterpret_cast<const float4*>(p + x * 4);
            s[x * 4]     += f.x;
            s[x * 4 + 1] += f.y;
            s[x * 4 + 2] += f.z;
            s[x * 4 + 3] += f.w;
        }
    }
    uint4 o0, o1;
    o0.x = pack_h2(s[1] * inv,  s[0] * inv);
    o0.y = pack_h2(s[3] * inv,  s[2] * inv);
    o0.z = pack_h2(s[5] * inv,  s[4] * inv);
    o0.w = pack_h2(s[7] * inv,  s[6] * inv);
    o1.x = pack_h2(s[9] * inv,  s[8] * inv);
    o1.y = pack_h2(s[11] * inv, s[10] * inv);
    o1.z = pack_h2(s[13] * inv, s[12] * inv);
    o1.w = pack_h2(s[15] * inv, s[14] * inv);
    __half* och = g_ctxh + head * DH * DH + base;
    *reinterpret_cast<uint4*>(och)     = o0;
    *reinterpret_cast<uint4*>(och + 8) = o1;
}

// ---------------------------------------------------------------------------
// Kernel 2: out[j,s] = (1/Zq_s) * sum_i ctxh[i][j] * exp(q[i,s])
// grid (SQ/128, NHEADS), block 256, one 64j x 128s tile per CTA.
// q batch-0 LDGs hoisted above ctx fetch; smem-transposed epilogue;
// streaming .cs output stores.
// ---------------------------------------------------------------------------
struct OutSmemPhase1 {
    __half sCt[64][72];    // [i][j] normalized half context
    __half sQ[64][136];    // [i][s] exp(q) half
    float  sZp[8][132];    // Zq partials
};
union OutSmem {
    OutSmemPhase1 p1;
    float sOut[64][132];   // epilogue staging [j][s]
};

__global__ __launch_bounds__(256, 4) void out_kernel(const float* __restrict__ q,
                                                     float* __restrict__ out) {
    __shared__ OutSmem sm;
    __shared__ float sCs[128];        // 1/Zq_s (persists across phases)

    const int head = blockIdx.y;
    const int s0   = blockIdx.x * 128;
    const int tid  = threadIdx.x;
    const int warp = tid >> 5;
    const int lane = tid & 31;

    const float* qg = q + (size_t)head * DH * SQ + s0;
    const int r  = tid >> 5;          // 0..7
    const int c4 = (tid & 31) * 4;    // 0..124

    // q batch 0 issued FIRST: DRAM latency covers the ctx L2 fetch below
    float4 qv0[4];
#pragma unroll
    for (int ib = 0; ib < 4; ++ib) {
        const int d = ib * 8 + r;
        qv0[ib] = *reinterpret_cast<const float4*>(qg + (size_t)d * SQ + c4);
    }

    // context tile: 256 threads x 2 uint4 = 8 KB (hits L2)
    {
        const uint4* src = reinterpret_cast<const uint4*>(g_ctxh + head * DH * DH);
        uint4 c0 = src[tid * 2];
        uint4 c1 = src[tid * 2 + 1];
        const int i = tid >> 2;
        const int j = (tid & 3) * 16;
        *reinterpret_cast<uint4*>(&sm.p1.sCt[i][j])     = c0;
        *reinterpret_cast<uint4*>(&sm.p1.sCt[i][j + 8]) = c1;
    }

    float4 zp = make_float4(0.f, 0.f, 0.f, 0.f);
    // convert batch 0
#pragma unroll
    for (int ib = 0; ib < 4; ++ib) {
        const int d = ib * 8 + r;
        uint2 eq;
        eq.x = ex2_h2(pack_h2(qv0[ib].y * LOG2E, qv0[ib].x * LOG2E));
        eq.y = ex2_h2(pack_h2(qv0[ib].w * LOG2E, qv0[ib].z * LOG2E));
        *reinterpret_cast<uint2*>(&sm.p1.sQ[d][c4]) = eq;
        float2 e0 = __half22float2(*reinterpret_cast<__half2*>(&eq.x));
        float2 e1 = __half22float2(*reinterpret_cast<__half2*>(&eq.y));
        zp.x += e0.x; zp.y += e0.y; zp.z += e1.x; zp.w += e1.y;
    }
    // q batch 1: load + convert
    {
        float4 qv1[4];
#pragma unroll
        for (int ib = 0; ib < 4; ++ib) {
            const int d = (4 + ib) * 8 + r;
            qv1[ib] = *reinterpret_cast<const float4*>(qg + (size_t)d * SQ + c4);
        }
#pragma unroll
        for (int ib = 0; ib < 4; ++ib) {
            const int d = (4 + ib) * 8 + r;
            uint2 eq;
            eq.x = ex2_h2(pack_h2(qv1[ib].y * LOG2E, qv1[ib].x * LOG2E));
            eq.y = ex2_h2(pack_h2(qv1[ib].w * LOG2E, qv1[ib].z * LOG2E));
            *reinterpret_cast<uint2*>(&sm.p1.sQ[d][c4]) = eq;
            float2 e0 = __half22float2(*reinterpret_cast<__half2*>(&eq.x));
            float2 e1 = __half22float2(*reinterpret_cast<__half2*>(&eq.y));
            zp.x += e0.x; zp.y += e0.y; zp.z += e1.x; zp.w += e1.y;
        }
    }
    *reinterpret_cast<float4*>(&sm.p1.sZp[r][c4]) = zp;
    __syncthreads();

    if (tid < 128) {
        float z = 0.0f;
#pragma unroll
        for (int d = 0; d < 8; ++d) z += sm.p1.sZp[d][tid];
        sCs[tid] = __fdividef(1.0f, z);
    }

    float acc[8][4];
#pragma unroll
    for (int n = 0; n < 8; ++n)
#pragma unroll
        for (int c = 0; c < 4; ++c) acc[n][c] = 0.0f;

    const int jw = (warp & 3) * 16;   // j offset
    const int sw = (warp >> 2) * 64;  // s offset

#pragma unroll
    for (int kk = 0; kk < 4; ++kk) {
        uint32_t a[4];
        ldsm_x4t(a, smem_u32(&sm.p1.sCt[kk * 16 + (lane & 7) + (lane >> 4) * 8]
                                        [jw + ((lane >> 3) & 1) * 8]));
#pragma unroll
        for (int np = 0; np < 4; ++np) {
            uint32_t b[4];
            ldsm_x4t(b, smem_u32(&sm.p1.sQ[kk * 16 + (lane & 7) + ((lane >> 3) & 1) * 8]
                                           [sw + (np * 2 + (lane >> 4)) * 8]));
            mma_f16(acc[np * 2],     a, b);
            mma_f16(acc[np * 2 + 1], a, b + 2);
        }
    }
    __syncthreads();   // sCs ready; sCt/sQ/sZp dead -> sOut may alias them

    // epilogue phase A: scale by 1/Zq_s, stage into smem [j][s]
    const int j0 = jw + (lane >> 2);
    const int sc = (lane & 3) * 2;
#pragma unroll
    for (int n = 0; n < 8; ++n) {
        const int s = sw + n * 8 + sc;
        const float inv0 = sCs[s];
        const float inv1 = sCs[s + 1];
        *reinterpret_cast<float2*>(&sm.sOut[j0][s]) =
            make_float2(acc[n][0] * inv0, acc[n][1] * inv1);
        *reinterpret_cast<float2*>(&sm.sOut[j0 + 8][s]) =
            make_float2(acc[n][2] * inv0, acc[n][3] * inv1);
    }
    __syncthreads();

    // epilogue phase B: coalesced streaming float4 stores (512B/warp-instr)
    float* og = out + (size_t)head * DH * SQ + s0;
#pragma unroll
    for (int ib = 0; ib < 8; ++ib) {
        const int d = ib * 8 + r;
        float4 wv = *reinterpret_cast<const float4*>(&sm.sOut[d][c4]);
        stg_cs_v4(og + (size_t)d * SQ + c4, wv);
    }
}

// ---------------------------------------------------------------------------
extern "C" void kernel_launch(void* const* d_in, const int* in_sizes, int n_in,
                              void* d_out, int out_size) {
    const float* q = (const float*)d_in[0];
    const float* k = (const float*)d_in[1];
    const float* v = (const float*)d_in[2];
    float* out = (float*)d_out;

    cudaFuncSetAttribute(ctx_kernel, cudaFuncAttributeMaxDynamicSharedMemorySize, CTX_SMEM);

    ctx_kernel<<<dim3(CHUNKS, NHEADS), 256, CTX_SMEM>>>(k, v);
    norm_kernel<<<NHEADS, 256>>>();
    out_kernel<<<dim3(SQ / 128, NHEADS), 256>>>(q, out);
}